// round 2
// baseline (speedup 1.0000x reference)
#include <cuda_runtime.h>
#include <cstdint>

// ---------------------------------------------------------------------------
// Problem constants
// ---------------------------------------------------------------------------
static constexpr int NROWS = 65536;
static constexpr int APPD  = 1024;
static constexpr int SPDIM = 512;

// CTA tile
static constexpr int BM = 128, BN = 128, BK = 32;
static constexpr int SMEM_FLOATS_BUF = (BM + BN) * BK;           // 8192 floats = 32KB
static constexpr int SMEM_BYTES      = 2 * SMEM_FLOATS_BUF * 4;  // 64KB (double buffer)

// ---------------------------------------------------------------------------
// Device scratch (allocation-free rule: __device__ globals)
// ---------------------------------------------------------------------------
__device__ float g_Bt1[512 * 1536];         // GEMM1 B: Bt1[n][k] = Wcat[k][n], tf32-rounded
__device__ float g_Bt2[512 * 512];          // GEMM2 B: Bt2[h][j] = W3flat[j][h], tf32-rounded
__device__ float g_bias1[512];              // b1 + b2 (flattened c*32+s)
__device__ float g_bias2[512];              // sum_c b3[c][:]
__device__ float g_H[(size_t)65536 * 512];  // intermediate h (tf32-rounded, fp32 container)

// ---------------------------------------------------------------------------
// Helpers (all plain sm_80+ PTX — no 'a'-gated instructions)
// ---------------------------------------------------------------------------
__device__ __forceinline__ uint32_t cvt_tf32(float f) {  // round-to-nearest tf32 bits
    uint32_t r;
    asm("cvt.rna.tf32.f32 %0, %1;" : "=r"(r) : "f"(f));
    return r;
}

__device__ __forceinline__ void cp16(uint32_t smem_dst, const void* gsrc) {
    asm volatile("cp.async.cg.shared.global [%0], [%1], 16;" :: "r"(smem_dst), "l"(gsrc));
}
__device__ __forceinline__ void cp_commit() { asm volatile("cp.async.commit_group;"); }
template <int N>
__device__ __forceinline__ void cp_wait() { asm volatile("cp.async.wait_group %0;" :: "n"(N)); }

// m16n8k8 tf32 mma. Fragment ownership (lane: g = lane>>2, c = lane&3):
//   a0=A[g][c]  a1=A[g+8][c]  a2=A[g][c+4]  a3=A[g+8][c+4]
//   b0=B[c][g]  b1=B[c+4][g]          (B col-major k x n)
//   d0=D[g][2c] d1=D[g][2c+1] d2=D[g+8][2c] d3=D[g+8][2c+1]
__device__ __forceinline__ void mma8(float* d, const uint32_t* a, uint32_t b0, uint32_t b1) {
    asm volatile(
        "mma.sync.aligned.m16n8k8.row.col.f32.tf32.tf32.f32 "
        "{%0,%1,%2,%3}, {%4,%5,%6,%7}, {%8,%9}, {%0,%1,%2,%3};"
        : "+f"(d[0]), "+f"(d[1]), "+f"(d[2]), "+f"(d[3])
        : "r"(a[0]), "r"(a[1]), "r"(a[2]), "r"(a[3]), "r"(b0), "r"(b1));
}

// ---------------------------------------------------------------------------
// Prep: transpose + tf32-round weights, fuse biases
// ---------------------------------------------------------------------------
__global__ void prep_kernel(const float* __restrict__ W1, const float* __restrict__ b1,
                            const float* __restrict__ W2, const float* __restrict__ b2,
                            const float* __restrict__ W3, const float* __restrict__ b3) {
    int idx = blockIdx.x * 256 + threadIdx.x;
    if (idx < 512 * 1536) {  // Bt1[n][k] = Wcat[k][n];  n = c*32+s
        int n = idx / 1536, k = idx % 1536;
        int c = n >> 5, s = n & 31;
        float v = (k < APPD) ? W1[((size_t)c * APPD + k) * 32 + s]
                             : W2[((size_t)c * SPDIM + (k - APPD)) * 32 + s];
        g_Bt1[idx] = __uint_as_float(cvt_tf32(v));
        return;
    }
    int i2 = idx - 512 * 1536;
    if (i2 < 512 * 512) {  // Bt2[h][j] = W3flat[j][h]
        int h = i2 / 512, j = i2 % 512;
        g_Bt2[i2] = __uint_as_float(cvt_tf32(W3[(size_t)j * 512 + h]));
        return;
    }
    int i3 = i2 - 512 * 512;
    if (i3 < 512) { g_bias1[i3] = b1[i3] + b2[i3]; return; }
    int i4 = i3 - 512;
    if (i4 < 512) {
        float s = 0.f;
        #pragma unroll
        for (int c = 0; c < 16; c++) s += b3[c * 512 + i4];
        g_bias2[i4] = s;
    }
}

// ---------------------------------------------------------------------------
// Tile loader: global -> SMEM via cp.async with XOR swizzle col' = col ^ 4*(row&7)
// (makes all fragment LDS patterns bank-conflict-free; 16B blocks preserved)
// ---------------------------------------------------------------------------
template <int MODE>
__device__ __forceinline__ void load_tile(int tid, int row0, int ncol0, int kt,
                                          float* As, float* Bs,
                                          const float* __restrict__ A0,
                                          const float* __restrict__ A1) {
    const float* abase;
    int lda;
    if (MODE == 1) {
        if (kt * BK < APPD) { abase = A0 + kt * BK; lda = APPD; }
        else                { abase = A1 + (kt * BK - APPD); lda = SPDIM; }
    } else {
        abase = g_H + kt * BK; lda = 512;
    }
    uint32_t as_s = (uint32_t)__cvta_generic_to_shared(As);
    uint32_t bs_s = (uint32_t)__cvta_generic_to_shared(Bs);
    #pragma unroll
    for (int i = 0; i < 8; i++) {   // A tile: 128 rows x 32 floats = 1024 vec4
        int v = i * 128 + tid;
        int r = v >> 3, q = v & 7;
        const float* src = abase + (size_t)(row0 + r) * lda + 4 * q;
        cp16(as_s + (uint32_t)(r * BK + ((4 * q) ^ (4 * (r & 7)))) * 4u, src);
    }
    const float* __restrict__ B = (MODE == 1) ? g_Bt1 : g_Bt2;
    const int ldb = (MODE == 1) ? 1536 : 512;
    #pragma unroll
    for (int i = 0; i < 8; i++) {   // B tile: 128 n-rows x 32 k
        int v = i * 128 + tid;
        int r = v >> 3, q = v & 7;
        const float* src = B + (size_t)(ncol0 + r) * ldb + kt * BK + 4 * q;
        cp16(bs_s + (uint32_t)(r * BK + ((4 * q) ^ (4 * (r & 7)))) * 4u, src);
    }
}

// ---------------------------------------------------------------------------
// GEMM: MODE 1: [X=app|sp] @ Bt1^T -> relu+bias -> g_H (tf32-rounded)
//       MODE 2: g_H @ Bt2^T -> relu+bias -> out
// CTA 128x128, 4 warps (2x2), warp tile 64x64.
// ---------------------------------------------------------------------------
template <int MODE>
__global__ void __launch_bounds__(128, 2)
gemm_tf32(const float* __restrict__ A0, const float* __restrict__ A1,
          float* __restrict__ outp) {
    extern __shared__ float smem[];
    const int tid = threadIdx.x;
    const int row0 = blockIdx.x * BM;
    const int ncol0 = blockIdx.y * BN;
    constexpr int NT = (MODE == 1) ? (1536 / BK) : (512 / BK);

    const int lane = tid & 31, wid = tid >> 5;
    const int m0 = (wid & 1) * 64;
    const int n0 = (wid >> 1) * 64;
    const int g = lane >> 2, c = lane & 3;

    // swizzled column offsets (loop-invariant)
    int off0[4], off4[4];
    #pragma unroll
    for (int j = 0; j < 4; j++) {
        off0[j] = (8 * j + c) ^ (4 * g);
        off4[j] = (8 * j + c + 4) ^ (4 * g);
    }

    float acc[4][8][4];
    #pragma unroll
    for (int mt = 0; mt < 4; mt++)
        #pragma unroll
        for (int nt = 0; nt < 8; nt++)
            #pragma unroll
            for (int q = 0; q < 4; q++) acc[mt][nt][q] = 0.f;

    float* buf0 = smem;
    float* buf1 = smem + SMEM_FLOATS_BUF;

    load_tile<MODE>(tid, row0, ncol0, 0, buf0, buf0 + BM * BK, A0, A1);
    cp_commit();

    for (int t = 0; t < NT; t++) {
        if (t + 1 < NT) {
            float* nb = ((t + 1) & 1) ? buf1 : buf0;
            load_tile<MODE>(tid, row0, ncol0, t + 1, nb, nb + BM * BK, A0, A1);
            cp_commit();
            cp_wait<1>();
        } else {
            cp_wait<0>();
        }
        __syncthreads();

        const float* As = (t & 1) ? buf1 : buf0;
        const float* Bs = As + BM * BK;

        #pragma unroll
        for (int j = 0; j < 4; j++) {
            uint32_t a[4][4];
            #pragma unroll
            for (int mt = 0; mt < 4; mt++) {
                const float* ar = As + (m0 + 16 * mt + g) * BK;
                float v0 = ar[off0[j]];
                float v1 = ar[8 * BK + off0[j]];
                float v2 = ar[off4[j]];
                float v3 = ar[8 * BK + off4[j]];
                if (MODE == 1) {  // raw fp32 inputs: round to tf32 (B & g_H pre-rounded)
                    a[mt][0] = cvt_tf32(v0); a[mt][1] = cvt_tf32(v1);
                    a[mt][2] = cvt_tf32(v2); a[mt][3] = cvt_tf32(v3);
                } else {
                    a[mt][0] = __float_as_uint(v0); a[mt][1] = __float_as_uint(v1);
                    a[mt][2] = __float_as_uint(v2); a[mt][3] = __float_as_uint(v3);
                }
            }
            #pragma unroll
            for (int nt = 0; nt < 8; nt++) {
                const float* br = Bs + (n0 + 8 * nt + g) * BK;
                uint32_t b0 = __float_as_uint(br[off0[j]]);
                uint32_t b1 = __float_as_uint(br[off4[j]]);
                #pragma unroll
                for (int mt = 0; mt < 4; mt++) mma8(acc[mt][nt], a[mt], b0, b1);
            }
        }
        __syncthreads();
    }

    // Epilogue: bias + relu (+ tf32 pre-round for g_H), direct STG
    const float* __restrict__ bias = (MODE == 1) ? g_bias1 : g_bias2;
    float* __restrict__ out = (MODE == 1) ? g_H : outp;
    #pragma unroll
    for (int nt = 0; nt < 8; nt++) {
        const int ccol = ncol0 + n0 + 8 * nt + 2 * c;
        const float2 bv = *(const float2*)(bias + ccol);
        #pragma unroll
        for (int mt = 0; mt < 4; mt++) {
            const int r_ = row0 + m0 + 16 * mt + g;
            float x0 = fmaxf(acc[mt][nt][0] + bv.x, 0.f);
            float x1 = fmaxf(acc[mt][nt][1] + bv.y, 0.f);
            float x2 = fmaxf(acc[mt][nt][2] + bv.x, 0.f);
            float x3 = fmaxf(acc[mt][nt][3] + bv.y, 0.f);
            if (MODE == 1) {
                x0 = __uint_as_float(cvt_tf32(x0));
                x1 = __uint_as_float(cvt_tf32(x1));
                x2 = __uint_as_float(cvt_tf32(x2));
                x3 = __uint_as_float(cvt_tf32(x3));
            }
            *(float2*)(out + (size_t)r_ * 512 + ccol)       = make_float2(x0, x1);
            *(float2*)(out + (size_t)(r_ + 8) * 512 + ccol) = make_float2(x2, x3);
        }
    }
}

// ---------------------------------------------------------------------------
// Launch
// ---------------------------------------------------------------------------
extern "C" void kernel_launch(void* const* d_in, const int* in_sizes, int n_in,
                              void* d_out, int out_size) {
    const float* app = (const float*)d_in[0];
    const float* sp  = (const float*)d_in[1];
    const float* W1  = (const float*)d_in[2];
    const float* b1  = (const float*)d_in[3];
    const float* W2  = (const float*)d_in[4];
    const float* b2  = (const float*)d_in[5];
    const float* W3  = (const float*)d_in[6];
    const float* b3  = (const float*)d_in[7];
    float* out = (float*)d_out;

    cudaFuncSetAttribute(gemm_tf32<1>, cudaFuncAttributeMaxDynamicSharedMemorySize, SMEM_BYTES);
    cudaFuncSetAttribute(gemm_tf32<2>, cudaFuncAttributeMaxDynamicSharedMemorySize, SMEM_BYTES);

    const int prep_elems = 512 * 1536 + 512 * 512 + 1024;
    prep_kernel<<<(prep_elems + 255) / 256, 256>>>(W1, b1, W2, b2, W3, b3);

    dim3 grid1(NROWS / BM, 512 / BN);  // (512, 4)
    gemm_tf32<1><<<grid1, 128, SMEM_BYTES>>>(app, sp, nullptr);
    gemm_tf32<2><<<grid1, 128, SMEM_BYTES>>>(nullptr, nullptr, out);
}

// round 3
// speedup vs baseline: 1.6660x; 1.6660x over previous
#include <cuda_runtime.h>
#include <cuda_fp16.h>
#include <cstdint>

// ---------------------------------------------------------------------------
// Problem constants
// ---------------------------------------------------------------------------
static constexpr int NROWS = 65536;
static constexpr int APPD  = 1024;
static constexpr int SPDIM = 512;

static constexpr int BM = 128, BN = 128, BK = 64;  // BK in k-elements

// MODE1: A fp32 (128x64x4=32KB) + B fp16 (128x64x2=16KB) per stage, x2 buffers
// MODE2: A fp16 (16KB) + B fp16 (16KB) per stage, x2
static constexpr int SMEM1 = 2 * (BM * BK * 4 + BN * BK * 2);  // 98304
static constexpr int SMEM2 = 2 * (BM * BK * 2 + BN * BK * 2);  // 65536

// ---------------------------------------------------------------------------
// Device scratch (allocation-free rule: __device__ globals)
// ---------------------------------------------------------------------------
__device__ __half g_B1h[512 * 1536];          // GEMM1 B: [n][k] = Wcat[k][n], fp16
__device__ __half g_B2h[512 * 512];           // GEMM2 B: [h][j] = W3flat[j][h], fp16
__device__ float  g_bias1[512];               // b1 + b2 (flattened c*32+s)
__device__ float  g_bias2[512];               // sum_c b3[c][:]
__device__ __half g_Hh[(size_t)65536 * 512];  // intermediate h, fp16

// ---------------------------------------------------------------------------
// Helpers (plain sm_80+ PTX only — nothing 'a'-gated)
// ---------------------------------------------------------------------------
__device__ __forceinline__ void cp16(uint32_t smem_dst, const void* gsrc) {
    asm volatile("cp.async.cg.shared.global [%0], [%1], 16;" :: "r"(smem_dst), "l"(gsrc));
}
__device__ __forceinline__ void cp_commit() { asm volatile("cp.async.commit_group;"); }
template <int N>
__device__ __forceinline__ void cp_wait() { asm volatile("cp.async.wait_group %0;" :: "n"(N)); }

__device__ __forceinline__ uint32_t pack_h2(float lo, float hi) {
    __half2 h = __floats2half2_rn(lo, hi);  // low = first arg
    return *reinterpret_cast<uint32_t*>(&h);
}

// m16n8k16 fp16 mma, fp32 accum. Lane (g = lane>>2, c = lane&3):
//   a0={A[g][2c],A[g][2c+1]} a1={A[g+8][2c..]} a2={A[g][2c+8..]} a3={A[g+8][2c+8..]}
//   b0={B[2c][g],B[2c+1][g]} b1={B[2c+8][g],B[2c+9][g]}   (B as [n][k] rows)
//   d0=D[g][2c] d1=D[g][2c+1] d2=D[g+8][2c] d3=D[g+8][2c+1]
__device__ __forceinline__ void mma16(float* d, const uint32_t* a, uint32_t b0, uint32_t b1) {
    asm volatile(
        "mma.sync.aligned.m16n8k16.row.col.f32.f16.f16.f32 "
        "{%0,%1,%2,%3}, {%4,%5,%6,%7}, {%8,%9}, {%0,%1,%2,%3};"
        : "+f"(d[0]), "+f"(d[1]), "+f"(d[2]), "+f"(d[3])
        : "r"(a[0]), "r"(a[1]), "r"(a[2]), "r"(a[3]), "r"(b0), "r"(b1));
}

// ---------------------------------------------------------------------------
// Prep: transpose weights -> fp16, fuse biases
// ---------------------------------------------------------------------------
__global__ void prep_kernel(const float* __restrict__ W1, const float* __restrict__ b1,
                            const float* __restrict__ W2, const float* __restrict__ b2,
                            const float* __restrict__ W3, const float* __restrict__ b3) {
    int idx = blockIdx.x * 256 + threadIdx.x;
    if (idx < 512 * 1536) {  // B1h[n][k] = Wcat[k][n];  n = c*32+s
        int n = idx / 1536, k = idx % 1536;
        int c = n >> 5, s = n & 31;
        float v = (k < APPD) ? W1[((size_t)c * APPD + k) * 32 + s]
                             : W2[((size_t)c * SPDIM + (k - APPD)) * 32 + s];
        g_B1h[idx] = __float2half_rn(v);
        return;
    }
    int i2 = idx - 512 * 1536;
    if (i2 < 512 * 512) {  // B2h[h][j] = W3flat[j][h]
        int h = i2 / 512, j = i2 % 512;
        g_B2h[i2] = __float2half_rn(W3[(size_t)j * 512 + h]);
        return;
    }
    int i3 = i2 - 512 * 512;
    if (i3 < 512) { g_bias1[i3] = b1[i3] + b2[i3]; return; }
    int i4 = i3 - 512;
    if (i4 < 512) {
        float s = 0.f;
        #pragma unroll
        for (int c = 0; c < 16; c++) s += b3[c * 512 + i4];
        g_bias2[i4] = s;
    }
}

// ---------------------------------------------------------------------------
// Tile loader: cp.async with XOR swizzle.
//   fp32 rows (256B): byte' = byte ^ 32*(row&7)
//   fp16 rows (128B): byte' = byte ^ 16*(row&7)
// (16B cp.async granularity preserved; fragment reads conflict-free)
// ---------------------------------------------------------------------------
template <int MODE>
__device__ __forceinline__ void load_tile(int tid, int row0, int ncol0, int kt,
                                          char* smemA, char* smemB,
                                          const float* __restrict__ A0,
                                          const float* __restrict__ A1) {
    uint32_t as_s = (uint32_t)__cvta_generic_to_shared(smemA);
    uint32_t bs_s = (uint32_t)__cvta_generic_to_shared(smemB);
    if (MODE == 1) {
        const float* abase; int lda;
        if (kt * BK < APPD) { abase = A0 + kt * BK; lda = APPD; }
        else                { abase = A1 + (kt * BK - APPD); lda = SPDIM; }
        #pragma unroll
        for (int i = 0; i < 16; i++) {  // 128 rows x 64 fp32 = 2048 x 16B
            int v = i * 128 + tid;
            int r = v >> 4, q = v & 15;
            cp16(as_s + (uint32_t)(r * 256 + ((16 * q) ^ (32 * (r & 7)))),
                 abase + (size_t)(row0 + r) * lda + 4 * q);
        }
    } else {
        #pragma unroll
        for (int i = 0; i < 8; i++) {   // 128 rows x 64 fp16 = 1024 x 16B
            int v = i * 128 + tid;
            int r = v >> 3, q = v & 7;
            cp16(as_s + (uint32_t)(r * 128 + ((16 * q) ^ (16 * (r & 7)))),
                 g_Hh + (size_t)(row0 + r) * 512 + kt * BK + 8 * q);
        }
    }
    const __half* __restrict__ B = (MODE == 1) ? g_B1h : g_B2h;
    const int ldb = (MODE == 1) ? 1536 : 512;
    #pragma unroll
    for (int i = 0; i < 8; i++) {
        int v = i * 128 + tid;
        int r = v >> 3, q = v & 7;
        cp16(bs_s + (uint32_t)(r * 128 + ((16 * q) ^ (16 * (r & 7)))),
             B + (size_t)(ncol0 + r) * ldb + kt * BK + 8 * q);
    }
}

// ---------------------------------------------------------------------------
// GEMM: MODE 1: [app|sp](fp32) @ B1h -> bias+relu -> g_Hh (fp16)
//       MODE 2: g_Hh @ B2h -> bias+relu -> out (fp32)
// CTA 128x128x64, 4 warps (2x2), warp tile 64x64, fp16 HMMA, fp32 accum.
// ---------------------------------------------------------------------------
template <int MODE>
__global__ void __launch_bounds__(128, 2)
gemm_h(const float* __restrict__ A0, const float* __restrict__ A1,
       float* __restrict__ outp) {
    extern __shared__ char smem[];
    constexpr int ABYTES = (MODE == 1) ? BM * BK * 4 : BM * BK * 2;
    constexpr int STAGE  = ABYTES + BN * BK * 2;
    constexpr int NT     = (MODE == 1) ? (1536 / BK) : (512 / BK);

    const int tid = threadIdx.x;
    const int row0 = blockIdx.x * BM;
    const int ncol0 = blockIdx.y * BN;
    const int lane = tid & 31, wid = tid >> 5;
    const int m0 = (wid & 1) * 64;
    const int n0 = (wid >> 1) * 64;
    const int g = lane >> 2, c = lane & 3;
    const int axor = (MODE == 1) ? 32 * (g & 7) : 16 * (g & 7);
    const int bxor = 16 * (g & 7);

    float acc[4][8][4];
    #pragma unroll
    for (int mt = 0; mt < 4; mt++)
        #pragma unroll
        for (int nt = 0; nt < 8; nt++)
            #pragma unroll
            for (int q = 0; q < 4; q++) acc[mt][nt][q] = 0.f;

    load_tile<MODE>(tid, row0, ncol0, 0, smem, smem + ABYTES, A0, A1);
    cp_commit();

    for (int t = 0; t < NT; t++) {
        if (t + 1 < NT) {
            char* nb = smem + ((t + 1) & 1) * STAGE;
            load_tile<MODE>(tid, row0, ncol0, t + 1, nb, nb + ABYTES, A0, A1);
            cp_commit();
            cp_wait<1>();
        } else {
            cp_wait<0>();
        }
        __syncthreads();

        const char* As = smem + (t & 1) * STAGE;
        const char* Bs = As + ABYTES;

        #pragma unroll
        for (int j = 0; j < 4; j++) {  // 4 x k16 per stage
            uint32_t a[4][4];
            #pragma unroll
            for (int mt = 0; mt < 4; mt++) {
                if (MODE == 1) {
                    const char* ar0 = As + (m0 + 16 * mt + g) * 256;
                    const char* ar1 = ar0 + 8 * 256;
                    float2 v0 = *(const float2*)(ar0 + ((8 * c + 64 * j) ^ axor));
                    float2 v1 = *(const float2*)(ar1 + ((8 * c + 64 * j) ^ axor));
                    float2 v2 = *(const float2*)(ar0 + ((8 * c + 64 * j + 32) ^ axor));
                    float2 v3 = *(const float2*)(ar1 + ((8 * c + 64 * j + 32) ^ axor));
                    a[mt][0] = pack_h2(v0.x, v0.y);
                    a[mt][1] = pack_h2(v1.x, v1.y);
                    a[mt][2] = pack_h2(v2.x, v2.y);
                    a[mt][3] = pack_h2(v3.x, v3.y);
                } else {
                    const char* ar0 = As + (m0 + 16 * mt + g) * 128;
                    const char* ar1 = ar0 + 8 * 128;
                    a[mt][0] = *(const uint32_t*)(ar0 + ((4 * c + 32 * j) ^ axor));
                    a[mt][1] = *(const uint32_t*)(ar1 + ((4 * c + 32 * j) ^ axor));
                    a[mt][2] = *(const uint32_t*)(ar0 + ((4 * c + 32 * j + 16) ^ axor));
                    a[mt][3] = *(const uint32_t*)(ar1 + ((4 * c + 32 * j + 16) ^ axor));
                }
            }
            #pragma unroll
            for (int nt = 0; nt < 8; nt++) {
                const char* br = Bs + (n0 + 8 * nt + g) * 128;
                uint32_t b0 = *(const uint32_t*)(br + ((4 * c + 32 * j) ^ bxor));
                uint32_t b1 = *(const uint32_t*)(br + ((4 * c + 32 * j + 16) ^ bxor));
                #pragma unroll
                for (int mt = 0; mt < 4; mt++) mma16(acc[mt][nt], a[mt], b0, b1);
            }
        }
        __syncthreads();
    }

    // Epilogue: bias + relu
    if (MODE == 1) {  // -> g_Hh (fp16)
        #pragma unroll
        for (int nt = 0; nt < 8; nt++) {
            const int ccol = ncol0 + n0 + 8 * nt + 2 * c;
            const float2 bv = *(const float2*)(g_bias1 + ccol);
            #pragma unroll
            for (int mt = 0; mt < 4; mt++) {
                const int r_ = row0 + m0 + 16 * mt + g;
                float x0 = fmaxf(acc[mt][nt][0] + bv.x, 0.f);
                float x1 = fmaxf(acc[mt][nt][1] + bv.y, 0.f);
                float x2 = fmaxf(acc[mt][nt][2] + bv.x, 0.f);
                float x3 = fmaxf(acc[mt][nt][3] + bv.y, 0.f);
                *(__half2*)(g_Hh + (size_t)r_ * 512 + ccol)       = __floats2half2_rn(x0, x1);
                *(__half2*)(g_Hh + (size_t)(r_ + 8) * 512 + ccol) = __floats2half2_rn(x2, x3);
            }
        }
    } else {          // -> out (fp32)
        #pragma unroll
        for (int nt = 0; nt < 8; nt++) {
            const int ccol = ncol0 + n0 + 8 * nt + 2 * c;
            const float2 bv = *(const float2*)(g_bias2 + ccol);
            #pragma unroll
            for (int mt = 0; mt < 4; mt++) {
                const int r_ = row0 + m0 + 16 * mt + g;
                float x0 = fmaxf(acc[mt][nt][0] + bv.x, 0.f);
                float x1 = fmaxf(acc[mt][nt][1] + bv.y, 0.f);
                float x2 = fmaxf(acc[mt][nt][2] + bv.x, 0.f);
                float x3 = fmaxf(acc[mt][nt][3] + bv.y, 0.f);
                *(float2*)(outp + (size_t)r_ * 512 + ccol)       = make_float2(x0, x1);
                *(float2*)(outp + (size_t)(r_ + 8) * 512 + ccol) = make_float2(x2, x3);
            }
        }
    }
}

// ---------------------------------------------------------------------------
// Launch
// ---------------------------------------------------------------------------
extern "C" void kernel_launch(void* const* d_in, const int* in_sizes, int n_in,
                              void* d_out, int out_size) {
    const float* app = (const float*)d_in[0];
    const float* sp  = (const float*)d_in[1];
    const float* W1  = (const float*)d_in[2];
    const float* b1  = (const float*)d_in[3];
    const float* W2  = (const float*)d_in[4];
    const float* b2  = (const float*)d_in[5];
    const float* W3  = (const float*)d_in[6];
    const float* b3  = (const float*)d_in[7];
    float* out = (float*)d_out;

    cudaFuncSetAttribute(gemm_h<1>, cudaFuncAttributeMaxDynamicSharedMemorySize, SMEM1);
    cudaFuncSetAttribute(gemm_h<2>, cudaFuncAttributeMaxDynamicSharedMemorySize, SMEM2);

    const int prep_elems = 512 * 1536 + 512 * 512 + 1024;
    prep_kernel<<<(prep_elems + 255) / 256, 256>>>(W1, b1, W2, b2, W3, b3);

    dim3 grid(NROWS / BM, 512 / BN);  // (512, 4)
    gemm_h<1><<<grid, 128, SMEM1>>>(app, sp, nullptr);
    gemm_h<2><<<grid, 128, SMEM2>>>(nullptr, nullptr, out);
}

// round 4
// speedup vs baseline: 1.7332x; 1.0404x over previous
#include <cuda_runtime.h>
#include <cuda_fp16.h>
#include <cstdint>

// ---------------------------------------------------------------------------
// Problem constants
// ---------------------------------------------------------------------------
static constexpr int NROWS = 65536;
static constexpr int APPD  = 1024;
static constexpr int SPDIM = 512;

static constexpr int BM = 128, BN = 128, BK = 64;  // BK in k-elements

// MODE1: A fp32 (128x64x4=32KB) + B fp16 (128x64x2=16KB) per stage, x2 buffers
// MODE2: A fp16 (16KB) + B fp16 (16KB) per stage, x2
static constexpr int SMEM1 = 2 * (BM * BK * 4 + BN * BK * 2);  // 98304
static constexpr int SMEM2 = 2 * (BM * BK * 2 + BN * BK * 2);  // 65536

// ---------------------------------------------------------------------------
// Device scratch (allocation-free rule: __device__ globals)
// ---------------------------------------------------------------------------
__device__ __half g_B1h[512 * 1536];          // GEMM1 B: [n][k] = Wcat[k][n], fp16
__device__ __half g_B2h[512 * 512];           // GEMM2 B: [h][j] = W3flat[j][h], fp16
__device__ float  g_bias1[512];               // b1 + b2 (flattened c*32+s)
__device__ float  g_bias2[512];               // sum_c b3[c][:]
__device__ __half g_Hh[(size_t)65536 * 512];  // intermediate h, fp16

// ---------------------------------------------------------------------------
// Helpers (plain sm_80+ PTX only — nothing 'a'-gated)
// ---------------------------------------------------------------------------
__device__ __forceinline__ void cp16(uint32_t smem_dst, const void* gsrc) {
    asm volatile("cp.async.cg.shared.global [%0], [%1], 16;" :: "r"(smem_dst), "l"(gsrc));
}
__device__ __forceinline__ void cp_commit() { asm volatile("cp.async.commit_group;"); }
template <int N>
__device__ __forceinline__ void cp_wait() { asm volatile("cp.async.wait_group %0;" :: "n"(N)); }

__device__ __forceinline__ uint32_t pack_h2(float lo, float hi) {
    __half2 h = __floats2half2_rn(lo, hi);  // low = first arg
    return *reinterpret_cast<uint32_t*>(&h);
}

// m16n8k16 fp16 mma, fp32 accum. Lane (g = lane>>2, c = lane&3):
//   a0={A[g][2c],A[g][2c+1]} a1={A[g+8][2c..]} a2={A[g][2c+8..]} a3={A[g+8][2c+8..]}
//   b0={B[2c][g],B[2c+1][g]} b1={B[2c+8][g],B[2c+9][g]}   (B as [n][k] rows)
//   d0=D[g][2c] d1=D[g][2c+1] d2=D[g+8][2c] d3=D[g+8][2c+1]
__device__ __forceinline__ void mma16(float* d, const uint32_t* a, uint32_t b0, uint32_t b1) {
    asm volatile(
        "mma.sync.aligned.m16n8k16.row.col.f32.f16.f16.f32 "
        "{%0,%1,%2,%3}, {%4,%5,%6,%7}, {%8,%9}, {%0,%1,%2,%3};"
        : "+f"(d[0]), "+f"(d[1]), "+f"(d[2]), "+f"(d[3])
        : "r"(a[0]), "r"(a[1]), "r"(a[2]), "r"(a[3]), "r"(b0), "r"(b1));
}

// ---------------------------------------------------------------------------
// Prep: transpose weights -> fp16, fuse biases
// ---------------------------------------------------------------------------
__global__ void prep_kernel(const float* __restrict__ W1, const float* __restrict__ b1,
                            const float* __restrict__ W2, const float* __restrict__ b2,
                            const float* __restrict__ W3, const float* __restrict__ b3) {
    int idx = blockIdx.x * 256 + threadIdx.x;
    if (idx < 512 * 1536) {  // B1h[n][k] = Wcat[k][n];  n = c*32+s
        int n = idx / 1536, k = idx % 1536;
        int c = n >> 5, s = n & 31;
        float v = (k < APPD) ? W1[((size_t)c * APPD + k) * 32 + s]
                             : W2[((size_t)c * SPDIM + (k - APPD)) * 32 + s];
        g_B1h[idx] = __float2half_rn(v);
        return;
    }
    int i2 = idx - 512 * 1536;
    if (i2 < 512 * 512) {  // B2h[h][j] = W3flat[j][h]
        int h = i2 / 512, j = i2 % 512;
        g_B2h[i2] = __float2half_rn(W3[(size_t)j * 512 + h]);
        return;
    }
    int i3 = i2 - 512 * 512;
    if (i3 < 512) { g_bias1[i3] = b1[i3] + b2[i3]; return; }
    int i4 = i3 - 512;
    if (i4 < 512) {
        float s = 0.f;
        #pragma unroll
        for (int c = 0; c < 16; c++) s += b3[c * 512 + i4];
        g_bias2[i4] = s;
    }
}

// ---------------------------------------------------------------------------
// Tile loader: cp.async with XOR swizzle.
//   fp32 rows (256B): byte' = byte ^ 32*(row&7)
//   fp16 rows (128B): byte' = byte ^ 16*(row&7)
// ---------------------------------------------------------------------------
template <int MODE>
__device__ __forceinline__ void load_tile(int tid, int row0, int ncol0, int kt,
                                          char* smemA, char* smemB,
                                          const float* __restrict__ A0,
                                          const float* __restrict__ A1) {
    uint32_t as_s = (uint32_t)__cvta_generic_to_shared(smemA);
    uint32_t bs_s = (uint32_t)__cvta_generic_to_shared(smemB);
    if (MODE == 1) {
        const float* abase; int lda;
        if (kt * BK < APPD) { abase = A0 + kt * BK; lda = APPD; }
        else                { abase = A1 + (kt * BK - APPD); lda = SPDIM; }
        #pragma unroll
        for (int i = 0; i < 16; i++) {  // 128 rows x 64 fp32 = 2048 x 16B
            int v = i * 128 + tid;
            int r = v >> 4, q = v & 15;
            cp16(as_s + (uint32_t)(r * 256 + ((16 * q) ^ (32 * (r & 7)))),
                 abase + (size_t)(row0 + r) * lda + 4 * q);
        }
    } else {
        #pragma unroll
        for (int i = 0; i < 8; i++) {   // 128 rows x 64 fp16 = 1024 x 16B
            int v = i * 128 + tid;
            int r = v >> 3, q = v & 7;
            cp16(as_s + (uint32_t)(r * 128 + ((16 * q) ^ (16 * (r & 7)))),
                 g_Hh + (size_t)(row0 + r) * 512 + kt * BK + 8 * q);
        }
    }
    const __half* __restrict__ B = (MODE == 1) ? g_B1h : g_B2h;
    const int ldb = (MODE == 1) ? 1536 : 512;
    #pragma unroll
    for (int i = 0; i < 8; i++) {
        int v = i * 128 + tid;
        int r = v >> 3, q = v & 7;
        cp16(bs_s + (uint32_t)(r * 128 + ((16 * q) ^ (16 * (r & 7)))),
             B + (size_t)(ncol0 + r) * ldb + kt * BK + 8 * q);
    }
}

// ---------------------------------------------------------------------------
// GEMM: MODE 1: [app|sp](fp32) @ B1h -> bias+relu -> g_Hh (fp16)
//       MODE 2: g_Hh @ B2h -> bias+relu -> out (fp32)
// CTA 128x128x64, 4 warps (2x2), warp tile 64x64, fp16 HMMA, fp32 accum.
// Grid is (n-blocks, row-blocks): same-A CTAs are schedule-adjacent -> L2 reuse.
// ---------------------------------------------------------------------------
template <int MODE>
__global__ void __launch_bounds__(128, 2)
gemm_h(const float* __restrict__ A0, const float* __restrict__ A1,
       float* __restrict__ outp) {
    extern __shared__ char smem[];
    constexpr int ABYTES = (MODE == 1) ? BM * BK * 4 : BM * BK * 2;
    constexpr int STAGE  = ABYTES + BN * BK * 2;
    constexpr int NT     = (MODE == 1) ? (1536 / BK) : (512 / BK);

    const int tid = threadIdx.x;
    const int ncol0 = blockIdx.x * BN;   // n fastest -> A-sharing CTAs co-resident
    const int row0  = blockIdx.y * BM;
    const int lane = tid & 31, wid = tid >> 5;
    const int m0 = (wid & 1) * 64;
    const int n0 = (wid >> 1) * 64;
    const int g = lane >> 2, c = lane & 3;
    const int axor = (MODE == 1) ? 32 * (g & 7) : 16 * (g & 7);
    const int bxor = 16 * (g & 7);

    float acc[4][8][4];
    #pragma unroll
    for (int mt = 0; mt < 4; mt++)
        #pragma unroll
        for (int nt = 0; nt < 8; nt++)
            #pragma unroll
            for (int q = 0; q < 4; q++) acc[mt][nt][q] = 0.f;

    load_tile<MODE>(tid, row0, ncol0, 0, smem, smem + ABYTES, A0, A1);
    cp_commit();

    for (int t = 0; t < NT; t++) {
        if (t + 1 < NT) {
            char* nb = smem + ((t + 1) & 1) * STAGE;
            load_tile<MODE>(tid, row0, ncol0, t + 1, nb, nb + ABYTES, A0, A1);
            cp_commit();
            cp_wait<1>();
        } else {
            cp_wait<0>();
        }
        __syncthreads();

        const char* As = smem + (t & 1) * STAGE;
        const char* Bs = As + ABYTES;

        #pragma unroll
        for (int j = 0; j < 4; j++) {  // 4 x k16 per stage
            uint32_t a[4][4];
            #pragma unroll
            for (int mt = 0; mt < 4; mt++) {
                if (MODE == 1) {
                    const char* ar0 = As + (m0 + 16 * mt + g) * 256;
                    const char* ar1 = ar0 + 8 * 256;
                    float2 v0 = *(const float2*)(ar0 + ((8 * c + 64 * j) ^ axor));
                    float2 v1 = *(const float2*)(ar1 + ((8 * c + 64 * j) ^ axor));
                    float2 v2 = *(const float2*)(ar0 + ((8 * c + 64 * j + 32) ^ axor));
                    float2 v3 = *(const float2*)(ar1 + ((8 * c + 64 * j + 32) ^ axor));
                    a[mt][0] = pack_h2(v0.x, v0.y);
                    a[mt][1] = pack_h2(v1.x, v1.y);
                    a[mt][2] = pack_h2(v2.x, v2.y);
                    a[mt][3] = pack_h2(v3.x, v3.y);
                } else {
                    const char* ar0 = As + (m0 + 16 * mt + g) * 128;
                    const char* ar1 = ar0 + 8 * 128;
                    a[mt][0] = *(const uint32_t*)(ar0 + ((4 * c + 32 * j) ^ axor));
                    a[mt][1] = *(const uint32_t*)(ar1 + ((4 * c + 32 * j) ^ axor));
                    a[mt][2] = *(const uint32_t*)(ar0 + ((4 * c + 32 * j + 16) ^ axor));
                    a[mt][3] = *(const uint32_t*)(ar1 + ((4 * c + 32 * j + 16) ^ axor));
                }
            }
            #pragma unroll
            for (int nt = 0; nt < 8; nt++) {
                const char* br = Bs + (n0 + 8 * nt + g) * 128;
                uint32_t b0 = *(const uint32_t*)(br + ((4 * c + 32 * j) ^ bxor));
                uint32_t b1 = *(const uint32_t*)(br + ((4 * c + 32 * j + 16) ^ bxor));
                #pragma unroll
                for (int mt = 0; mt < 4; mt++) mma16(acc[mt][nt], a[mt], b0, b1);
            }
        }
        __syncthreads();
    }

    // Epilogue: bias + relu
    if (MODE == 1) {  // -> g_Hh (fp16)
        #pragma unroll
        for (int nt = 0; nt < 8; nt++) {
            const int ccol = ncol0 + n0 + 8 * nt + 2 * c;
            const float2 bv = *(const float2*)(g_bias1 + ccol);
            #pragma unroll
            for (int mt = 0; mt < 4; mt++) {
                const int r_ = row0 + m0 + 16 * mt + g;
                float x0 = fmaxf(acc[mt][nt][0] + bv.x, 0.f);
                float x1 = fmaxf(acc[mt][nt][1] + bv.y, 0.f);
                float x2 = fmaxf(acc[mt][nt][2] + bv.x, 0.f);
                float x3 = fmaxf(acc[mt][nt][3] + bv.y, 0.f);
                *(__half2*)(g_Hh + (size_t)r_ * 512 + ccol)       = __floats2half2_rn(x0, x1);
                *(__half2*)(g_Hh + (size_t)(r_ + 8) * 512 + ccol) = __floats2half2_rn(x2, x3);
            }
        }
    } else {          // -> out (fp32)
        #pragma unroll
        for (int nt = 0; nt < 8; nt++) {
            const int ccol = ncol0 + n0 + 8 * nt + 2 * c;
            const float2 bv = *(const float2*)(g_bias2 + ccol);
            #pragma unroll
            for (int mt = 0; mt < 4; mt++) {
                const int r_ = row0 + m0 + 16 * mt + g;
                float x0 = fmaxf(acc[mt][nt][0] + bv.x, 0.f);
                float x1 = fmaxf(acc[mt][nt][1] + bv.y, 0.f);
                float x2 = fmaxf(acc[mt][nt][2] + bv.x, 0.f);
                float x3 = fmaxf(acc[mt][nt][3] + bv.y, 0.f);
                *(float2*)(outp + (size_t)r_ * 512 + ccol)       = make_float2(x0, x1);
                *(float2*)(outp + (size_t)(r_ + 8) * 512 + ccol) = make_float2(x2, x3);
            }
        }
    }
}

// ---------------------------------------------------------------------------
// Launch
// ---------------------------------------------------------------------------
extern "C" void kernel_launch(void* const* d_in, const int* in_sizes, int n_in,
                              void* d_out, int out_size) {
    const float* app = (const float*)d_in[0];
    const float* sp  = (const float*)d_in[1];
    const float* W1  = (const float*)d_in[2];
    const float* b1  = (const float*)d_in[3];
    const float* W2  = (const float*)d_in[4];
    const float* b2  = (const float*)d_in[5];
    const float* W3  = (const float*)d_in[6];
    const float* b3  = (const float*)d_in[7];
    float* out = (float*)d_out;

    cudaFuncSetAttribute(gemm_h<1>, cudaFuncAttributeMaxDynamicSharedMemorySize, SMEM1);
    cudaFuncSetAttribute(gemm_h<2>, cudaFuncAttributeMaxDynamicSharedMemorySize, SMEM2);

    const int prep_elems = 512 * 1536 + 512 * 512 + 1024;
    prep_kernel<<<(prep_elems + 255) / 256, 256>>>(W1, b1, W2, b2, W3, b3);

    dim3 grid(512 / BN, NROWS / BM);  // (4, 512): n-blocks fastest -> A L2 reuse
    gemm_h<1><<<grid, 128, SMEM1>>>(app, sp, nullptr);
    gemm_h<2><<<grid, 128, SMEM2>>>(nullptr, nullptr, out);
}